// round 11
// baseline (speedup 1.0000x reference)
#include <cuda_runtime.h>

// ---------------- static config ----------------
#define NCAM   6
#define FC     128
#define FH     32
#define FW     88
#define NPIX   (FH*FW)          // 2816
#define DLEV   41
#define OC3    170
#define OUTC   128
#define G_TOT  (NCAM*NPIX)      // 16896
#define BEV_H  100
#define BEV_W  100
#define P_TOT  (BEV_H*BEV_W)
#define KTOT   (9*FC)
#define NSEG   4

// ---------------- scratch ----------------
__device__ float g_x1[NCAM*FC*NPIX];
__device__ float g_x2[NCAM*FC*NPIX];
__device__ float g_logits[NCAM*OC3*NPIX];
__device__ float g_colors[G_TOT*OUTC];
__device__ float g_wt1[KTOT*FC];
__device__ float g_wt2[KTOT*FC];
__device__ float4 g_pk0[G_TOT], g_pk1[G_TOT];
__device__ int   g_rmin[G_TOT], g_rmax[G_TOT];
__device__ int   g_list[BEV_H*G_TOT];
__device__ int   g_len[BEV_H];
__device__ float g_sacc[NSEG][P_TOT*OUTC];
__device__ float g_sT[NSEG][P_TOT];
__device__ float g_cam[NCAM*24];
__device__ float g_sc1[FC], g_sh1[FC], g_sc2[FC], g_sh2[FC];
__device__ int   g_cnt;

// ---------------- setup ----------------
__device__ __forceinline__ void inv3(const float* m, float* o) {
    float a=m[0],b=m[1],c=m[2],d=m[3],e=m[4],f=m[5],g=m[6],h=m[7],i=m[8];
    float A =  (e*i - f*h);
    float B = -(d*i - f*g);
    float C =  (d*h - e*g);
    float det = a*A + b*B + c*C;
    float id = 1.0f/det;
    o[0]=A*id;            o[1]=-(b*i-c*h)*id;  o[2]= (b*f-c*e)*id;
    o[3]=B*id;            o[4]= (a*i-c*g)*id;  o[5]=-(a*f-c*d)*id;
    o[6]=C*id;            o[7]=-(a*h-b*g)*id;  o[8]= (a*e-b*d)*id;
}

__global__ void k_setup(const float* __restrict__ rots, const float* __restrict__ trans,
                        const float* __restrict__ intr, const float* __restrict__ prots,
                        const float* __restrict__ ptrans,
                        const float* __restrict__ c1b, const float* __restrict__ g1,
                        const float* __restrict__ b1,  const float* __restrict__ m1,
                        const float* __restrict__ v1,
                        const float* __restrict__ c2b, const float* __restrict__ g2,
                        const float* __restrict__ b2,  const float* __restrict__ m2,
                        const float* __restrict__ v2) {
    int t = threadIdx.x;
    if (t < NCAM) {
        float iK[9], iPR[9], comb[9];
        inv3(intr + t*9, iK);
        inv3(prots + t*9, iPR);
        const float* R = rots + t*9;
        #pragma unroll
        for (int r = 0; r < 3; r++)
            #pragma unroll
            for (int c = 0; c < 3; c++)
                comb[r*3+c] = R[r*3+0]*iK[0*3+c] + R[r*3+1]*iK[1*3+c] + R[r*3+2]*iK[2*3+c];
        float* o = g_cam + t*24;
        #pragma unroll
        for (int j = 0; j < 9; j++) o[j]   = comb[j];
        #pragma unroll
        for (int j = 0; j < 9; j++) o[9+j] = iPR[j];
        o[18]=trans[t*3+0]; o[19]=trans[t*3+1]; o[20]=trans[t*3+2];
        o[21]=ptrans[t*3+0]; o[22]=ptrans[t*3+1]; o[23]=ptrans[t*3+2];
    }
    if (t < FC) {
        float s1 = g1[t]*rsqrtf(v1[t] + 1e-3f);
        g_sc1[t] = s1;
        g_sh1[t] = (c1b[t] - m1[t])*s1 + b1[t];
        float s2 = g2[t]*rsqrtf(v2[t] + 1e-3f);
        g_sc2[t] = s2;
        g_sh2[t] = (c2b[t] - m2[t])*s2 + b2[t];
    }
    if (t == 0) g_cnt = 0;
}

// ---------------- weight transpose ----------------
__global__ void k_wtrans(const float* __restrict__ w1, const float* __restrict__ w2) {
    int i = blockIdx.x * 256 + threadIdx.x;
    int k  = i >> 7, oc = i & 127;
    int s  = k >> 7, ic = k & 127;
    int src = oc*KTOT + ic*9 + s;
    g_wt1[i] = w1[src];
    g_wt2[i] = w2[src];
}

// ---------------- conv3x3 implicit GEMM: 128oc x 64px tile, 512 threads ---------
// grid (44 px-tiles, 6 images), block 512 = 32x16, micro-tile 4 oc x 4 px.
__global__ void __launch_bounds__(512, 2) k_conv3g(const float* __restrict__ feats, int layer) {
    __shared__ float sW[16][128];
    __shared__ float sX[16][64];
    const float* in_ = layer ? g_x1 : feats;
    const float* wt  = layer ? g_wt2 : g_wt1;
    float*       out = layer ? g_x2  : g_x1;
    const float* sc  = layer ? g_sc2 : g_sc1;
    const float* sh  = layer ? g_sh2 : g_sh1;

    int p0 = blockIdx.x * 64;
    int n  = blockIdx.y;
    int tid = threadIdx.x;
    int tx = tid & 15;     // px quad
    int ty = tid >> 4;     // oc quad (0..31)

    float acc[4][4];
    #pragma unroll
    for (int i = 0; i < 4; i++)
        #pragma unroll
        for (int j = 0; j < 4; j++) acc[i][j] = 0.0f;

    const float* inBase = in_ + n*FC*NPIX;

    // staging coords (s-invariant)
    int kkW = tid >> 5, cvW = tid & 31;          // 1 float4 of W per thread
    int kkU[2], ppU[2], hU[2], wU[2];
    #pragma unroll
    for (int u = 0; u < 2; u++) {
        int e  = tid + u*512;
        kkU[u] = e >> 6; ppU[u] = e & 63;
        int p = p0 + ppU[u];
        hU[u] = p / FW; wU[u] = p - hU[u]*FW;
    }

    for (int s = 0; s < 9; s++) {
        int dh = s/3 - 1, dw = s%3 - 1;
        int doff = dh*FW + dw;
        bool valU[2];
        #pragma unroll
        for (int u = 0; u < 2; u++) {
            int hh = hU[u] + dh, ww = wU[u] + dw;
            valU[u] = ((unsigned)hh < FH) && ((unsigned)ww < FW);
        }
        for (int ic0 = 0; ic0 < FC; ic0 += 16) {
            __syncthreads();
            {
                int k0 = s*FC + ic0;
                ((float4*)&sW[kkW][0])[cvW] = ((const float4*)&wt[(k0+kkW)*FC])[cvW];
            }
            #pragma unroll
            for (int u = 0; u < 2; u++) {
                float v = valU[u] ? inBase[(ic0+kkU[u])*NPIX + p0 + ppU[u] + doff] : 0.0f;
                sX[kkU[u]][ppU[u]] = v;
            }
            __syncthreads();
            #pragma unroll
            for (int kk = 0; kk < 16; kk++) {
                float4 xv = *(const float4*)&sX[kk][tx*4];
                float4 wv = *(const float4*)&sW[kk][ty*4];
                float xr[4] = {xv.x,xv.y,xv.z,xv.w};
                float wr[4] = {wv.x,wv.y,wv.z,wv.w};
                #pragma unroll
                for (int i = 0; i < 4; i++)
                    #pragma unroll
                    for (int j = 0; j < 4; j++)
                        acc[i][j] = fmaf(wr[i], xr[j], acc[i][j]);
            }
        }
    }

    #pragma unroll
    for (int i = 0; i < 4; i++) {
        int oc = ty*4 + i;
        float scv = sc[oc], shv = sh[oc];
        float* op_ = out + (n*FC + oc)*NPIX + p0 + tx*4;
        #pragma unroll
        for (int j = 0; j < 4; j++)
            op_[j] = fmaxf(fmaf(acc[i][j], scv, shv), 0.0f);
    }
}

// ---------------- conv1x1 tiled GEMM ----------------
__global__ void k_conv1x1(const float* __restrict__ w3, const float* __restrict__ b3) {
    __shared__ float sW[16][64];
    __shared__ float sX[16][64];
    int p0  = blockIdx.x * 64;
    int oc0 = blockIdx.y * 64;
    int n   = blockIdx.z;
    int tid = threadIdx.x;
    int tx  = tid & 15;
    int ty  = tid >> 4;

    float acc[4][4];
    #pragma unroll
    for (int i = 0; i < 4; i++)
        #pragma unroll
        for (int j = 0; j < 4; j++) acc[i][j] = 0.0f;

    for (int k0 = 0; k0 < FC; k0 += 16) {
        #pragma unroll
        for (int i = tid; i < 16*64; i += 256) {
            int kk = i >> 6, oc = i & 63;
            int ocg = oc0 + oc;
            sW[kk][oc] = (ocg < OC3) ? w3[ocg*FC + k0 + kk] : 0.0f;
        }
        #pragma unroll
        for (int i = tid; i < 16*64; i += 256) {
            int kk = i >> 6, pp = i & 63;
            sX[kk][pp] = g_x2[(n*FC + k0 + kk)*NPIX + p0 + pp];
        }
        __syncthreads();
        #pragma unroll
        for (int kk = 0; kk < 16; kk++) {
            float xv[4], wv[4];
            #pragma unroll
            for (int j = 0; j < 4; j++) xv[j] = sX[kk][tx*4 + j];
            #pragma unroll
            for (int i = 0; i < 4; i++) wv[i] = sW[kk][ty*4 + i];
            #pragma unroll
            for (int i = 0; i < 4; i++)
                #pragma unroll
                for (int j = 0; j < 4; j++)
                    acc[i][j] = fmaf(wv[i], xv[j], acc[i][j]);
        }
        __syncthreads();
    }
    #pragma unroll
    for (int i = 0; i < 4; i++) {
        int oc = oc0 + ty*4 + i;
        if (oc < OC3) {
            float bb = __ldg(&b3[oc]);
            #pragma unroll
            for (int j = 0; j < 4; j++)
                g_logits[(n*OC3 + oc)*NPIX + p0 + tx*4 + j] = acc[i][j] + bb;
        }
    }
}

// ---------------- gaussian prep ----------------
__global__ void k_gauss() {
    int g = blockIdx.x * 128 + threadIdx.x;
    int n = g / NPIX;
    int p = g - n*NPIX;
    int h = p / FW;
    int w = p - h*FW;
    const float* L = g_logits + n*OC3*NPIX + p;

    float lg[DLEV];
    float mval = -1e30f;
    #pragma unroll
    for (int d = 0; d < DLEV; d++) { lg[d] = L[d*NPIX]; mval = fmaxf(mval, lg[d]); }
    float sum = 0.0f;
    #pragma unroll
    for (int d = 0; d < DLEV; d++) { lg[d] = __expf(lg[d] - mval); sum += lg[d]; }
    float inv = 1.0f / sum;

    const float* cm = g_cam + n*24;
    float c00=cm[0], c01=cm[1], c02=cm[2], c10=cm[3], c11=cm[4], c12=cm[5];
    float i00=cm[9], i01=cm[10], i02=cm[11], i10=cm[12], i11=cm[13], i12=cm[14];
    float i20=cm[15], i21=cm[16], i22=cm[17];
    float tx=cm[18], ty=cm[19];
    float ptx=cm[21], pty=cm[22], ptz=cm[23];
    float xs = (float)w * (703.0f/87.0f);
    float ys = (float)h * (255.0f/31.0f);
    float b0 = xs - ptx, b1 = ys - pty, b2 = -ptz;
    float bx = i00*b0 + i01*b1 + i02*b2;
    float by = i10*b0 + i11*b1 + i12*b2;
    float bz = i20*b0 + i21*b1 + i22*b2;
    float dx = i02, dy = i12, dz = i22;

    float mex = 0.0f, mey = 0.0f;
    #pragma unroll
    for (int d = 0; d < DLEV; d++) {
        float dep = 4.0f + (float)d;
        float p1x = bx + dep*dx, p1y = by + dep*dy, p1z = bz + dep*dz;
        float p2x = p1x*p1z, p2y = p1y*p1z;
        float gx = c00*p2x + c01*p2y + c02*p1z + tx;
        float gy = c10*p2x + c11*p2y + c12*p1z + ty;
        float pr = lg[d]*inv;
        mex += pr*gx; mey += pr*gy;
    }
    float cxx = 0.0f, cxy = 0.0f, cyy = 0.0f;
    #pragma unroll
    for (int d = 0; d < DLEV; d++) {
        float dep = 4.0f + (float)d;
        float p1x = bx + dep*dx, p1y = by + dep*dy, p1z = bz + dep*dz;
        float p2x = p1x*p1z, p2y = p1y*p1z;
        float gx = c00*p2x + c01*p2y + c02*p1z + tx;
        float gy = c10*p2x + c11*p2y + c12*p1z + ty;
        float ddx = mex - gx, ddy = mey - gy;
        float pr = lg[d]*inv;
        cxx += pr*ddx*ddx; cxy += pr*ddx*ddy; cyy += pr*ddy*ddy;
    }
    float a_ = cyy*(1.0f/9.0f) + 0.3f;
    float c_ = cxx*(1.0f/9.0f) + 0.3f;
    float b_ = cxy*(1.0f/9.0f);
    float det = a_*c_ - b_*b_;

    float opl = L[DLEV*NPIX];
    float op = 1.0f / (1.0f + __expf(-opl));
    bool msk = (op > 0.05f);
    if (msk) atomicAdd(&g_cnt, 1);
    bool valid = msk && (det > 0.0f);
    float idet = valid ? (1.0f/det) : 0.0f;

    float my = 50.0f - mey;
    float mx = 50.0f - mex;
    float qm = valid ? 2.0f*logf(255.0f*op) : -1e30f;

    g_pk0[g] = make_float4(my, mx, c_*idet, -b_*idet);
    g_pk1[g] = make_float4(a_*idet, op, qm, 0.0f);

    int r0 = 1, r1 = 0;
    if (valid) {
        float ext = sqrtf(fmaxf(qm, 0.0f)*a_) + 0.6f;
        r0 = max(0,  (int)ceilf(my - ext));
        r1 = min(99, (int)floorf(my + ext));
    }
    g_rmin[g] = r0;
    g_rmax[g] = r1;

    float4* cp4 = (float4*)(g_colors + g*OUTC);
    const float* fp_ = L + (DLEV+1)*NPIX;
    #pragma unroll
    for (int c = 0; c < OUTC; c += 4) {
        float4 v;
        v.x = fp_[(c+0)*NPIX];
        v.y = fp_[(c+1)*NPIX];
        v.z = fp_[(c+2)*NPIX];
        v.w = fp_[(c+3)*NPIX];
        cp4[c >> 2] = v;
    }
}

// ---------------- per-row ordered list build ----------------
__global__ void k_rows() {
    int r = blockIdx.x;
    int tid = threadIdx.x, lane = tid & 31, wid = tid >> 5;
    __shared__ int sCnt[8];
    __shared__ int sOff, sTot;
    if (tid == 0) sOff = 0;
    __syncthreads();
    for (int base = 0; base < G_TOT; base += 256) {
        int g = base + tid;
        bool f = (g_rmin[g] <= r) && (r <= g_rmax[g]);
        unsigned b = __ballot_sync(0xffffffffu, f);
        if (lane == 0) sCnt[wid] = __popc(b);
        __syncthreads();
        if (tid == 0) {
            int t = 0;
            #pragma unroll
            for (int i = 0; i < 8; i++) { int c = sCnt[i]; sCnt[i] = t; t += c; }
            sTot = t;
        }
        __syncthreads();
        if (f) {
            int pos = sOff + sCnt[wid] + __popc(b & ((1u << lane) - 1u));
            g_list[r*G_TOT + pos] = g;
        }
        __syncthreads();
        if (tid == 0) sOff += sTot;
        __syncthreads();
    }
    if (tid == 0) g_len[r] = sOff;
}

// ---------------- splat: scan weights -> smem, block-level color GEMM ----------
// grid (100 rows, NSEG), block 416 = 13 warps. (round-9 measured-best config)
__global__ void k_splat4() {
    int r   = blockIdx.x;
    int seg = blockIdx.y;
    int tid  = threadIdx.x;
    int warp = tid >> 5;
    int lane = tid & 31;
    int col0 = warp * 8;
    float fi = (float)r;

    int px = tid % 104;
    int tq = tid / 104;          // 0..3

    float pj[8], T[8];
    #pragma unroll
    for (int k = 0; k < 8; k++) {
        int c = col0 + k;
        pj[k] = (c < BEV_W) ? (float)c : 1e15f;
        T[k]  = 1.0f;
    }
    float acc[8][4];
    #pragma unroll
    for (int j = 0; j < 8; j++)
        #pragma unroll
        for (int jj = 0; jj < 4; jj++) acc[j][jj] = 0.0f;

    __shared__ int   sGid[32];
    __shared__ float sP[32][8];
    __shared__ float wBuf[32][105];
    __shared__ float cBuf[32][128];

    int len = g_len[r];
    int s0 = (len * seg) / NSEG;
    int s1 = (len * (seg+1)) / NSEG;
    const int* lst = g_list + r*G_TOT;

    for (int c0 = s0; c0 < s1; c0 += 32) {
        __syncthreads();
        if (tid < 32) {
            int idx = c0 + tid;
            if (idx < s1) {
                int gid = lst[idx];
                sGid[tid] = gid;
                float4 a = g_pk0[gid];
                float4 b = g_pk1[gid];
                sP[tid][0] = a.x; sP[tid][1] = a.y;
                sP[tid][2] = a.z; sP[tid][3] = a.w;
                sP[tid][4] = b.x; sP[tid][5] = b.y;
                sP[tid][6] = b.z;
            } else {
                sGid[tid] = 0;
                sP[tid][0] = 0.0f; sP[tid][1] = 0.0f;
                sP[tid][2] = 0.0f; sP[tid][3] = 0.0f;
                sP[tid][4] = 0.0f; sP[tid][5] = 0.0f;
                sP[tid][6] = -1e30f;
            }
        }
        __syncthreads();
        for (int i = tid; i < 1024; i += 416) {
            int g = i >> 5, cv = i & 31;
            *(float4*)&cBuf[g][cv*4] = *(const float4*)(g_colors + sGid[g]*OUTC + cv*4);
        }

        // phase A: ordered weights via multiplicative scan
        float my = sP[lane][0], mxx = sP[lane][1];
        float A  = sP[lane][2], Bc  = sP[lane][3], Cc = sP[lane][4];
        float op = sP[lane][5], qm  = sP[lane][6];
        float dI = fi - my;
        float c1 = A*dI*dI;
        float c2 = 2.0f*Bc*dI;

        float al[8]; unsigned msk[8];
        #pragma unroll
        for (int k = 0; k < 8; k++) {
            float dJ = pj[k] - mxx;
            float q = c1 + c2*dJ + Cc*dJ*dJ;
            float a_v = 0.0f;
            if (q >= 0.0f && q <= qm + 1e-3f) {
                a_v = fminf(0.99f, op*__expf(-0.5f*q));
                if (a_v < (1.0f/255.0f)) a_v = 0.0f;
            }
            al[k] = a_v;
            msk[k] = __ballot_sync(0xffffffffu, a_v > 0.0f);
        }
        #pragma unroll
        for (int k = 0; k < 8; k++) {
            float wv = 0.0f;
            if (msk[k]) {
                float incl = 1.0f - al[k];
                #pragma unroll
                for (int off = 1; off < 32; off <<= 1) {
                    float u = __shfl_up_sync(0xffffffffu, incl, off);
                    if (lane >= off) incl *= u;
                }
                float excl = __shfl_up_sync(0xffffffffu, incl, 1);
                if (lane == 0) excl = 1.0f;
                wv = al[k] * T[k] * excl;
                T[k] *= __shfl_sync(0xffffffffu, incl, 31);
            }
            wBuf[lane][col0 + k] = wv;
        }
        __syncthreads();

        // phase B: dense color GEMM with ballot skip
        #pragma unroll 4
        for (int g = 0; g < 32; g++) {
            float w = wBuf[g][px];
            if (__ballot_sync(0xffffffffu, w != 0.0f)) {
                #pragma unroll
                for (int j = 0; j < 8; j++) {
                    float4 col = *(const float4*)&cBuf[g][tq*4 + j*16];
                    acc[j][0] = fmaf(w, col.x, acc[j][0]);
                    acc[j][1] = fmaf(w, col.y, acc[j][1]);
                    acc[j][2] = fmaf(w, col.z, acc[j][2]);
                    acc[j][3] = fmaf(w, col.w, acc[j][3]);
                }
            }
        }
    }

    if (px < BEV_W) {
        int p = r*BEV_W + px;
        #pragma unroll
        for (int j = 0; j < 8; j++) {
            int cq = tq + 4*j;
            #pragma unroll
            for (int jj = 0; jj < 4; jj++)
                g_sacc[seg][(cq*4 + jj)*P_TOT + p] = acc[j][jj];
        }
    }
    if (lane == 0) {
        #pragma unroll
        for (int k = 0; k < 8; k++) {
            int c = col0 + k;
            if (c < BEV_W) g_sT[seg][r*BEV_W + c] = T[k];
        }
    }
}

// ---------------- combine segments ----------------
__global__ void k_combine(float* __restrict__ out) {
    int i = blockIdx.x * 256 + threadIdx.x;
    int p = i % P_TOT;
    float v = g_sacc[NSEG-1][i];
    #pragma unroll
    for (int s = NSEG-2; s >= 0; s--)
        v = g_sacc[s][i] + g_sT[s][p] * v;
    out[i] = v;
}

__global__ void k_count(float* __restrict__ dst) {
    dst[0] = (float)g_cnt;
}

// ---------------- launch ----------------
extern "C" void kernel_launch(void* const* d_in, const int* in_sizes, int n_in,
                              void* d_out, int out_size) {
    const float* rots   = (const float*)d_in[0];
    const float* trans  = (const float*)d_in[1];
    const float* intr   = (const float*)d_in[2];
    const float* prots  = (const float*)d_in[3];
    const float* ptrans = (const float*)d_in[4];
    const float* feats  = (const float*)d_in[5];
    const float* c1w = (const float*)d_in[6];
    const float* c1b = (const float*)d_in[7];
    const float* g1  = (const float*)d_in[8];
    const float* b1  = (const float*)d_in[9];
    const float* m1  = (const float*)d_in[10];
    const float* v1  = (const float*)d_in[11];
    const float* c2w = (const float*)d_in[12];
    const float* c2b = (const float*)d_in[13];
    const float* g2  = (const float*)d_in[14];
    const float* b2  = (const float*)d_in[15];
    const float* m2  = (const float*)d_in[16];
    const float* v2  = (const float*)d_in[17];
    const float* c3w = (const float*)d_in[18];
    const float* c3b = (const float*)d_in[19];
    float* out = (float*)d_out;

    k_setup<<<1, 256>>>(rots, trans, intr, prots, ptrans,
                        c1b, g1, b1, m1, v1, c2b, g2, b2, m2, v2);
    k_wtrans<<<576, 256>>>(c1w, c2w);
    k_conv3g<<<dim3(44, 6), 512>>>(feats, 0);
    k_conv3g<<<dim3(44, 6), 512>>>(feats, 1);
    k_conv1x1<<<dim3(44, 3, 6), 256>>>(c3w, c3b);
    k_gauss<<<132, 128>>>();
    k_rows<<<BEV_H, 256>>>();
    k_splat4<<<dim3(BEV_H, NSEG), 416>>>();
    k_combine<<<5000, 256>>>(out);
    if (out_size > P_TOT*OUTC)
        k_count<<<1, 1>>>(out + P_TOT*OUTC);
}

// round 12
// speedup vs baseline: 1.0162x; 1.0162x over previous
#include <cuda_runtime.h>

// ---------------- static config ----------------
#define NCAM   6
#define FC     128
#define FH     32
#define FW     88
#define NPIX   (FH*FW)          // 2816
#define DLEV   41
#define OC3    170
#define OUTC   128
#define G_TOT  (NCAM*NPIX)      // 16896
#define BEV_H  100
#define BEV_W  100
#define P_TOT  (BEV_H*BEV_W)
#define KTOT   (9*FC)
#define NSEG   4

// packed fp32x2 FMA (FFMA2): d = a*b + d, per-lane IEEE fp32 exact
#define FMA2(acc, x, w) \
    asm("fma.rn.f32x2 %0, %1, %2, %3;" : "=l"(acc) : "l"(x), "l"(w), "l"(acc))
#define PACK2(d, f) \
    asm("mov.b64 %0, {%1, %2};" : "=l"(d) : "f"(f), "f"(f))

// ---------------- scratch ----------------
__device__ float g_x1[NCAM*FC*NPIX];
__device__ float g_x2[NCAM*FC*NPIX];
__device__ float g_logits[NCAM*OC3*NPIX];
__device__ float g_colors[G_TOT*OUTC];
__device__ float g_wtd1[KTOT*2*FC];         // duplicated-pair weights [k][2*oc+{0,1}]
__device__ float g_wtd2[KTOT*2*FC];
__device__ float4 g_pk0[G_TOT], g_pk1[G_TOT];
__device__ int   g_rmin[G_TOT], g_rmax[G_TOT];
__device__ int   g_list[BEV_H*G_TOT];
__device__ int   g_len[BEV_H];
__device__ float g_sacc[NSEG][P_TOT*OUTC];
__device__ float g_sT[NSEG][P_TOT];
__device__ float g_cam[NCAM*24];
__device__ float g_sc1[FC], g_sh1[FC], g_sc2[FC], g_sh2[FC];
__device__ int   g_cnt;

// ---------------- setup ----------------
__device__ __forceinline__ void inv3(const float* m, float* o) {
    float a=m[0],b=m[1],c=m[2],d=m[3],e=m[4],f=m[5],g=m[6],h=m[7],i=m[8];
    float A =  (e*i - f*h);
    float B = -(d*i - f*g);
    float C =  (d*h - e*g);
    float det = a*A + b*B + c*C;
    float id = 1.0f/det;
    o[0]=A*id;            o[1]=-(b*i-c*h)*id;  o[2]= (b*f-c*e)*id;
    o[3]=B*id;            o[4]= (a*i-c*g)*id;  o[5]=-(a*f-c*d)*id;
    o[6]=C*id;            o[7]=-(a*h-b*g)*id;  o[8]= (a*e-b*d)*id;
}

__global__ void k_setup(const float* __restrict__ rots, const float* __restrict__ trans,
                        const float* __restrict__ intr, const float* __restrict__ prots,
                        const float* __restrict__ ptrans,
                        const float* __restrict__ c1b, const float* __restrict__ g1,
                        const float* __restrict__ b1,  const float* __restrict__ m1,
                        const float* __restrict__ v1,
                        const float* __restrict__ c2b, const float* __restrict__ g2,
                        const float* __restrict__ b2,  const float* __restrict__ m2,
                        const float* __restrict__ v2) {
    int t = threadIdx.x;
    if (t < NCAM) {
        float iK[9], iPR[9], comb[9];
        inv3(intr + t*9, iK);
        inv3(prots + t*9, iPR);
        const float* R = rots + t*9;
        #pragma unroll
        for (int r = 0; r < 3; r++)
            #pragma unroll
            for (int c = 0; c < 3; c++)
                comb[r*3+c] = R[r*3+0]*iK[0*3+c] + R[r*3+1]*iK[1*3+c] + R[r*3+2]*iK[2*3+c];
        float* o = g_cam + t*24;
        #pragma unroll
        for (int j = 0; j < 9; j++) o[j]   = comb[j];
        #pragma unroll
        for (int j = 0; j < 9; j++) o[9+j] = iPR[j];
        o[18]=trans[t*3+0]; o[19]=trans[t*3+1]; o[20]=trans[t*3+2];
        o[21]=ptrans[t*3+0]; o[22]=ptrans[t*3+1]; o[23]=ptrans[t*3+2];
    }
    if (t < FC) {
        float s1 = g1[t]*rsqrtf(v1[t] + 1e-3f);
        g_sc1[t] = s1;
        g_sh1[t] = (c1b[t] - m1[t])*s1 + b1[t];
        float s2 = g2[t]*rsqrtf(v2[t] + 1e-3f);
        g_sc2[t] = s2;
        g_sh2[t] = (c2b[t] - m2[t])*s2 + b2[t];
    }
    if (t == 0) g_cnt = 0;
}

// ---------------- weight transpose + duplicate: [oc][ic][3][3] -> [k][2*oc+{0,1}] --
__global__ void k_wtrans(const float* __restrict__ w1, const float* __restrict__ w2) {
    int i = blockIdx.x * 256 + threadIdx.x;     // 1152 blocks, exact KTOT*256
    int k  = i >> 8, j = i & 255;
    int oc = j >> 1;
    int s  = k >> 7, ic = k & 127;
    int src = oc*KTOT + ic*9 + s;
    g_wtd1[i] = w1[src];
    g_wtd2[i] = w2[src];
}

// ---------------- conv3x3 implicit GEMM, f32x2 inner loop --------------------
// grid (44 px-tiles, 6 images), block 256 = 16x16, micro-tile 8 oc x 4 px.
__global__ void k_conv3g(const float* __restrict__ feats, int layer) {
    __shared__ __align__(16) float sW[16][256];   // duplicated pairs
    __shared__ __align__(16) float sX[16][64];
    const float* in_ = layer ? g_x1 : feats;
    const float* wt  = layer ? g_wtd2 : g_wtd1;
    float*       out = layer ? g_x2  : g_x1;
    const float* sc  = layer ? g_sc2 : g_sc1;
    const float* sh  = layer ? g_sh2 : g_sh1;

    int p0 = blockIdx.x * 64;
    int n  = blockIdx.y;
    int tid = threadIdx.x;
    int tx = tid & 15;     // px quad
    int ty = tid >> 4;     // oc oct

    unsigned long long accP[8][2];
    #pragma unroll
    for (int i = 0; i < 8; i++) { accP[i][0] = 0ULL; accP[i][1] = 0ULL; }

    const float* inBase = in_ + n*FC*NPIX;

    int kkU[4], ppU[4], hU[4], wU[4];
    #pragma unroll
    for (int u = 0; u < 4; u++) {
        int e  = tid + u*256;
        kkU[u] = e >> 6; ppU[u] = e & 63;
        int p = p0 + ppU[u];
        hU[u] = p / FW; wU[u] = p - hU[u]*FW;
    }

    for (int s = 0; s < 9; s++) {
        int dh = s/3 - 1, dw = s%3 - 1;
        int doff = dh*FW + dw;
        bool valU[4];
        #pragma unroll
        for (int u = 0; u < 4; u++) {
            int hh = hU[u] + dh, ww = wU[u] + dw;
            valU[u] = ((unsigned)hh < FH) && ((unsigned)ww < FW);
        }
        for (int ic0 = 0; ic0 < FC; ic0 += 16) {
            __syncthreads();
            // stage W: 16 rows x 256 floats (dup pairs) = 1024 float4
            {
                int k0 = s*FC + ic0;
                #pragma unroll
                for (int u = 0; u < 4; u++) {
                    int e  = tid + u*256;
                    int kk = e >> 6, cv = e & 63;
                    ((float4*)&sW[kk][0])[cv] = ((const float4*)&wt[(k0+kk)*256])[cv];
                }
            }
            #pragma unroll
            for (int u = 0; u < 4; u++) {
                float v = valU[u] ? inBase[(ic0+kkU[u])*NPIX + p0 + ppU[u] + doff] : 0.0f;
                sX[kkU[u]][ppU[u]] = v;
            }
            __syncthreads();
            #pragma unroll
            for (int kk = 0; kk < 16; kk++) {
                ulonglong2 xd = *(const ulonglong2*)&sX[kk][tx*4];   // {x0,x1},{x2,x3}
                const ulonglong2* wrow = (const ulonglong2*)&sW[kk][ty*16];
                ulonglong2 wd0 = wrow[0];   // {w0,w0},{w1,w1}
                ulonglong2 wd1 = wrow[1];
                ulonglong2 wd2 = wrow[2];
                ulonglong2 wd3 = wrow[3];
                FMA2(accP[0][0], xd.x, wd0.x); FMA2(accP[0][1], xd.y, wd0.x);
                FMA2(accP[1][0], xd.x, wd0.y); FMA2(accP[1][1], xd.y, wd0.y);
                FMA2(accP[2][0], xd.x, wd1.x); FMA2(accP[2][1], xd.y, wd1.x);
                FMA2(accP[3][0], xd.x, wd1.y); FMA2(accP[3][1], xd.y, wd1.y);
                FMA2(accP[4][0], xd.x, wd2.x); FMA2(accP[4][1], xd.y, wd2.x);
                FMA2(accP[5][0], xd.x, wd2.y); FMA2(accP[5][1], xd.y, wd2.y);
                FMA2(accP[6][0], xd.x, wd3.x); FMA2(accP[6][1], xd.y, wd3.x);
                FMA2(accP[7][0], xd.x, wd3.y); FMA2(accP[7][1], xd.y, wd3.y);
            }
        }
    }

    #pragma unroll
    for (int i = 0; i < 8; i++) {
        int oc = ty*8 + i;
        float scv = sc[oc], shv = sh[oc];
        float2 lo = *(float2*)&accP[i][0];
        float2 hi = *(float2*)&accP[i][1];
        float* op_ = out + (n*FC + oc)*NPIX + p0 + tx*4;
        op_[0] = fmaxf(fmaf(lo.x, scv, shv), 0.0f);
        op_[1] = fmaxf(fmaf(lo.y, scv, shv), 0.0f);
        op_[2] = fmaxf(fmaf(hi.x, scv, shv), 0.0f);
        op_[3] = fmaxf(fmaf(hi.y, scv, shv), 0.0f);
    }
}

// ---------------- conv1x1 tiled GEMM ----------------
__global__ void k_conv1x1(const float* __restrict__ w3, const float* __restrict__ b3) {
    __shared__ float sW[16][64];
    __shared__ float sX[16][64];
    int p0  = blockIdx.x * 64;
    int oc0 = blockIdx.y * 64;
    int n   = blockIdx.z;
    int tid = threadIdx.x;
    int tx  = tid & 15;
    int ty  = tid >> 4;

    float acc[4][4];
    #pragma unroll
    for (int i = 0; i < 4; i++)
        #pragma unroll
        for (int j = 0; j < 4; j++) acc[i][j] = 0.0f;

    for (int k0 = 0; k0 < FC; k0 += 16) {
        #pragma unroll
        for (int i = tid; i < 16*64; i += 256) {
            int kk = i >> 6, oc = i & 63;
            int ocg = oc0 + oc;
            sW[kk][oc] = (ocg < OC3) ? w3[ocg*FC + k0 + kk] : 0.0f;
        }
        #pragma unroll
        for (int i = tid; i < 16*64; i += 256) {
            int kk = i >> 6, pp = i & 63;
            sX[kk][pp] = g_x2[(n*FC + k0 + kk)*NPIX + p0 + pp];
        }
        __syncthreads();
        #pragma unroll
        for (int kk = 0; kk < 16; kk++) {
            float xv[4], wv[4];
            #pragma unroll
            for (int j = 0; j < 4; j++) xv[j] = sX[kk][tx*4 + j];
            #pragma unroll
            for (int i = 0; i < 4; i++) wv[i] = sW[kk][ty*4 + i];
            #pragma unroll
            for (int i = 0; i < 4; i++)
                #pragma unroll
                for (int j = 0; j < 4; j++)
                    acc[i][j] = fmaf(wv[i], xv[j], acc[i][j]);
        }
        __syncthreads();
    }
    #pragma unroll
    for (int i = 0; i < 4; i++) {
        int oc = oc0 + ty*4 + i;
        if (oc < OC3) {
            float bb = __ldg(&b3[oc]);
            #pragma unroll
            for (int j = 0; j < 4; j++)
                g_logits[(n*OC3 + oc)*NPIX + p0 + tx*4 + j] = acc[i][j] + bb;
        }
    }
}

// ---------------- gaussian prep ----------------
__global__ void k_gauss() {
    int g = blockIdx.x * 128 + threadIdx.x;
    int n = g / NPIX;
    int p = g - n*NPIX;
    int h = p / FW;
    int w = p - h*FW;
    const float* L = g_logits + n*OC3*NPIX + p;

    float lg[DLEV];
    float mval = -1e30f;
    #pragma unroll
    for (int d = 0; d < DLEV; d++) { lg[d] = L[d*NPIX]; mval = fmaxf(mval, lg[d]); }
    float sum = 0.0f;
    #pragma unroll
    for (int d = 0; d < DLEV; d++) { lg[d] = __expf(lg[d] - mval); sum += lg[d]; }
    float inv = 1.0f / sum;

    const float* cm = g_cam + n*24;
    float c00=cm[0], c01=cm[1], c02=cm[2], c10=cm[3], c11=cm[4], c12=cm[5];
    float i00=cm[9], i01=cm[10], i02=cm[11], i10=cm[12], i11=cm[13], i12=cm[14];
    float i20=cm[15], i21=cm[16], i22=cm[17];
    float tx=cm[18], ty=cm[19];
    float ptx=cm[21], pty=cm[22], ptz=cm[23];
    float xs = (float)w * (703.0f/87.0f);
    float ys = (float)h * (255.0f/31.0f);
    float b0 = xs - ptx, b1 = ys - pty, b2 = -ptz;
    float bx = i00*b0 + i01*b1 + i02*b2;
    float by = i10*b0 + i11*b1 + i12*b2;
    float bz = i20*b0 + i21*b1 + i22*b2;
    float dx = i02, dy = i12, dz = i22;

    float mex = 0.0f, mey = 0.0f;
    #pragma unroll
    for (int d = 0; d < DLEV; d++) {
        float dep = 4.0f + (float)d;
        float p1x = bx + dep*dx, p1y = by + dep*dy, p1z = bz + dep*dz;
        float p2x = p1x*p1z, p2y = p1y*p1z;
        float gx = c00*p2x + c01*p2y + c02*p1z + tx;
        float gy = c10*p2x + c11*p2y + c12*p1z + ty;
        float pr = lg[d]*inv;
        mex += pr*gx; mey += pr*gy;
    }
    float cxx = 0.0f, cxy = 0.0f, cyy = 0.0f;
    #pragma unroll
    for (int d = 0; d < DLEV; d++) {
        float dep = 4.0f + (float)d;
        float p1x = bx + dep*dx, p1y = by + dep*dy, p1z = bz + dep*dz;
        float p2x = p1x*p1z, p2y = p1y*p1z;
        float gx = c00*p2x + c01*p2y + c02*p1z + tx;
        float gy = c10*p2x + c11*p2y + c12*p1z + ty;
        float ddx = mex - gx, ddy = mey - gy;
        float pr = lg[d]*inv;
        cxx += pr*ddx*ddx; cxy += pr*ddx*ddy; cyy += pr*ddy*ddy;
    }
    float a_ = cyy*(1.0f/9.0f) + 0.3f;
    float c_ = cxx*(1.0f/9.0f) + 0.3f;
    float b_ = cxy*(1.0f/9.0f);
    float det = a_*c_ - b_*b_;

    float opl = L[DLEV*NPIX];
    float op = 1.0f / (1.0f + __expf(-opl));
    bool msk = (op > 0.05f);
    if (msk) atomicAdd(&g_cnt, 1);
    bool valid = msk && (det > 0.0f);
    float idet = valid ? (1.0f/det) : 0.0f;

    float my = 50.0f - mey;
    float mx = 50.0f - mex;
    float qm = valid ? 2.0f*logf(255.0f*op) : -1e30f;

    g_pk0[g] = make_float4(my, mx, c_*idet, -b_*idet);
    g_pk1[g] = make_float4(a_*idet, op, qm, 0.0f);

    int r0 = 1, r1 = 0;
    if (valid) {
        float ext = sqrtf(fmaxf(qm, 0.0f)*a_) + 0.6f;
        r0 = max(0,  (int)ceilf(my - ext));
        r1 = min(99, (int)floorf(my + ext));
    }
    g_rmin[g] = r0;
    g_rmax[g] = r1;

    float4* cp4 = (float4*)(g_colors + g*OUTC);
    const float* fp_ = L + (DLEV+1)*NPIX;
    #pragma unroll
    for (int c = 0; c < OUTC; c += 4) {
        float4 v;
        v.x = fp_[(c+0)*NPIX];
        v.y = fp_[(c+1)*NPIX];
        v.z = fp_[(c+2)*NPIX];
        v.w = fp_[(c+3)*NPIX];
        cp4[c >> 2] = v;
    }
}

// ---------------- per-row ordered list build ----------------
__global__ void k_rows() {
    int r = blockIdx.x;
    int tid = threadIdx.x, lane = tid & 31, wid = tid >> 5;
    __shared__ int sCnt[8];
    __shared__ int sOff, sTot;
    if (tid == 0) sOff = 0;
    __syncthreads();
    for (int base = 0; base < G_TOT; base += 256) {
        int g = base + tid;
        bool f = (g_rmin[g] <= r) && (r <= g_rmax[g]);
        unsigned b = __ballot_sync(0xffffffffu, f);
        if (lane == 0) sCnt[wid] = __popc(b);
        __syncthreads();
        if (tid == 0) {
            int t = 0;
            #pragma unroll
            for (int i = 0; i < 8; i++) { int c = sCnt[i]; sCnt[i] = t; t += c; }
            sTot = t;
        }
        __syncthreads();
        if (f) {
            int pos = sOff + sCnt[wid] + __popc(b & ((1u << lane) - 1u));
            g_list[r*G_TOT + pos] = g;
        }
        __syncthreads();
        if (tid == 0) sOff += sTot;
        __syncthreads();
    }
    if (tid == 0) g_len[r] = sOff;
}

// ---------------- splat: scan weights -> smem, f32x2 color GEMM ----------------
// grid (100 rows, NSEG), block 416 = 13 warps.
__global__ void k_splat4() {
    int r   = blockIdx.x;
    int seg = blockIdx.y;
    int tid  = threadIdx.x;
    int warp = tid >> 5;
    int lane = tid & 31;
    int col0 = warp * 8;
    float fi = (float)r;

    int px = tid % 104;
    int tq = tid / 104;          // 0..3

    float pj[8], T[8];
    #pragma unroll
    for (int k = 0; k < 8; k++) {
        int c = col0 + k;
        pj[k] = (c < BEV_W) ? (float)c : 1e15f;
        T[k]  = 1.0f;
    }
    unsigned long long accP[8][2];
    #pragma unroll
    for (int j = 0; j < 8; j++) { accP[j][0] = 0ULL; accP[j][1] = 0ULL; }

    __shared__ int   sGid[32];
    __shared__ float sP[32][8];
    __shared__ __align__(16) float wBuf[32][105];
    __shared__ __align__(16) float cBuf[32][128];

    int len = g_len[r];
    int s0 = (len * seg) / NSEG;
    int s1 = (len * (seg+1)) / NSEG;
    const int* lst = g_list + r*G_TOT;

    for (int c0 = s0; c0 < s1; c0 += 32) {
        __syncthreads();
        if (tid < 32) {
            int idx = c0 + tid;
            if (idx < s1) {
                int gid = lst[idx];
                sGid[tid] = gid;
                float4 a = g_pk0[gid];
                float4 b = g_pk1[gid];
                sP[tid][0] = a.x; sP[tid][1] = a.y;
                sP[tid][2] = a.z; sP[tid][3] = a.w;
                sP[tid][4] = b.x; sP[tid][5] = b.y;
                sP[tid][6] = b.z;
            } else {
                sGid[tid] = 0;
                sP[tid][0] = 0.0f; sP[tid][1] = 0.0f;
                sP[tid][2] = 0.0f; sP[tid][3] = 0.0f;
                sP[tid][4] = 0.0f; sP[tid][5] = 0.0f;
                sP[tid][6] = -1e30f;
            }
        }
        __syncthreads();
        for (int i = tid; i < 1024; i += 416) {
            int g = i >> 5, cv = i & 31;
            *(float4*)&cBuf[g][cv*4] = *(const float4*)(g_colors + sGid[g]*OUTC + cv*4);
        }

        // phase A: ordered weights via multiplicative scan
        float my = sP[lane][0], mxx = sP[lane][1];
        float A  = sP[lane][2], Bc  = sP[lane][3], Cc = sP[lane][4];
        float op = sP[lane][5], qm  = sP[lane][6];
        float dI = fi - my;
        float c1 = A*dI*dI;
        float c2 = 2.0f*Bc*dI;

        float al[8]; unsigned msk[8];
        #pragma unroll
        for (int k = 0; k < 8; k++) {
            float dJ = pj[k] - mxx;
            float q = c1 + c2*dJ + Cc*dJ*dJ;
            float a_v = 0.0f;
            if (q >= 0.0f && q <= qm + 1e-3f) {
                a_v = fminf(0.99f, op*__expf(-0.5f*q));
                if (a_v < (1.0f/255.0f)) a_v = 0.0f;
            }
            al[k] = a_v;
            msk[k] = __ballot_sync(0xffffffffu, a_v > 0.0f);
        }
        #pragma unroll
        for (int k = 0; k < 8; k++) {
            float wv = 0.0f;
            if (msk[k]) {
                float incl = 1.0f - al[k];
                #pragma unroll
                for (int off = 1; off < 32; off <<= 1) {
                    float u = __shfl_up_sync(0xffffffffu, incl, off);
                    if (lane >= off) incl *= u;
                }
                float excl = __shfl_up_sync(0xffffffffu, incl, 1);
                if (lane == 0) excl = 1.0f;
                wv = al[k] * T[k] * excl;
                T[k] *= __shfl_sync(0xffffffffu, incl, 31);
            }
            wBuf[lane][col0 + k] = wv;
        }
        __syncthreads();

        // phase B: f32x2 color GEMM with ballot skip
        #pragma unroll 4
        for (int g = 0; g < 32; g++) {
            float w = wBuf[g][px];
            if (__ballot_sync(0xffffffffu, w != 0.0f)) {
                unsigned long long wd;
                PACK2(wd, w);
                #pragma unroll
                for (int j = 0; j < 8; j++) {
                    ulonglong2 cd = *(const ulonglong2*)&cBuf[g][tq*4 + j*16];
                    FMA2(accP[j][0], cd.x, wd);
                    FMA2(accP[j][1], cd.y, wd);
                }
            }
        }
    }

    if (px < BEV_W) {
        int p = r*BEV_W + px;
        #pragma unroll
        for (int j = 0; j < 8; j++) {
            int cq = tq + 4*j;
            float2 lo = *(float2*)&accP[j][0];
            float2 hi = *(float2*)&accP[j][1];
            g_sacc[seg][(cq*4 + 0)*P_TOT + p] = lo.x;
            g_sacc[seg][(cq*4 + 1)*P_TOT + p] = lo.y;
            g_sacc[seg][(cq*4 + 2)*P_TOT + p] = hi.x;
            g_sacc[seg][(cq*4 + 3)*P_TOT + p] = hi.y;
        }
    }
    if (lane == 0) {
        #pragma unroll
        for (int k = 0; k < 8; k++) {
            int c = col0 + k;
            if (c < BEV_W) g_sT[seg][r*BEV_W + c] = T[k];
        }
    }
}

// ---------------- combine segments ----------------
__global__ void k_combine(float* __restrict__ out) {
    int i = blockIdx.x * 256 + threadIdx.x;
    int p = i % P_TOT;
    float v = g_sacc[NSEG-1][i];
    #pragma unroll
    for (int s = NSEG-2; s >= 0; s--)
        v = g_sacc[s][i] + g_sT[s][p] * v;
    out[i] = v;
}

__global__ void k_count(float* __restrict__ dst) {
    dst[0] = (float)g_cnt;
}

// ---------------- launch ----------------
extern "C" void kernel_launch(void* const* d_in, const int* in_sizes, int n_in,
                              void* d_out, int out_size) {
    const float* rots   = (const float*)d_in[0];
    const float* trans  = (const float*)d_in[1];
    const float* intr   = (const float*)d_in[2];
    const float* prots  = (const float*)d_in[3];
    const float* ptrans = (const float*)d_in[4];
    const float* feats  = (const float*)d_in[5];
    const float* c1w = (const float*)d_in[6];
    const float* c1b = (const float*)d_in[7];
    const float* g1  = (const float*)d_in[8];
    const float* b1  = (const float*)d_in[9];
    const float* m1  = (const float*)d_in[10];
    const float* v1  = (const float*)d_in[11];
    const float* c2w = (const float*)d_in[12];
    const float* c2b = (const float*)d_in[13];
    const float* g2  = (const float*)d_in[14];
    const float* b2  = (const float*)d_in[15];
    const float* m2  = (const float*)d_in[16];
    const float* v2  = (const float*)d_in[17];
    const float* c3w = (const float*)d_in[18];
    const float* c3b = (const float*)d_in[19];
    float* out = (float*)d_out;

    k_setup<<<1, 256>>>(rots, trans, intr, prots, ptrans,
                        c1b, g1, b1, m1, v1, c2b, g2, b2, m2, v2);
    k_wtrans<<<1152, 256>>>(c1w, c2w);
    k_conv3g<<<dim3(44, 6), 256>>>(feats, 0);
    k_conv3g<<<dim3(44, 6), 256>>>(feats, 1);
    k_conv1x1<<<dim3(44, 3, 6), 256>>>(c3w, c3b);
    k_gauss<<<132, 128>>>();
    k_rows<<<BEV_H, 256>>>();
    k_splat4<<<dim3(BEV_H, NSEG), 416>>>();
    k_combine<<<5000, 256>>>(out);
    if (out_size > P_TOT*OUTC)
        k_count<<<1, 1>>>(out + P_TOT*OUTC);
}

// round 13
// speedup vs baseline: 1.2543x; 1.2344x over previous
#include <cuda_runtime.h>

// ---------------- static config ----------------
#define NCAM   6
#define FC     128
#define FH     32
#define FW     88
#define NPIX   (FH*FW)          // 2816
#define DLEV   41
#define OC3    170
#define OUTC   128
#define G_TOT  (NCAM*NPIX)      // 16896
#define BEV_H  100
#define BEV_W  100
#define P_TOT  (BEV_H*BEV_W)
#define KTOT   (9*FC)
#define NSEG   4

// ---------------- scratch ----------------
__device__ float g_x1[NCAM*FC*NPIX];
__device__ float g_x2[NCAM*FC*NPIX];
__device__ float g_logits[NCAM*OC3*NPIX];
__device__ float g_colors[G_TOT*OUTC];
__device__ float g_wt1[KTOT*FC];
__device__ float g_wt2[KTOT*FC];
__device__ float4 g_pk0[G_TOT], g_pk1[G_TOT];
__device__ int   g_rmin[G_TOT], g_rmax[G_TOT];
__device__ int   g_list[BEV_H*G_TOT];
__device__ int   g_len[BEV_H];
__device__ float g_sacc[NSEG][P_TOT*OUTC];
__device__ float g_sT[NSEG][P_TOT];
__device__ float g_cam[NCAM*24];
__device__ float g_sc1[FC], g_sh1[FC], g_sc2[FC], g_sh2[FC];
__device__ int   g_cnt;

// ---------------- setup ----------------
__device__ __forceinline__ void inv3(const float* m, float* o) {
    float a=m[0],b=m[1],c=m[2],d=m[3],e=m[4],f=m[5],g=m[6],h=m[7],i=m[8];
    float A =  (e*i - f*h);
    float B = -(d*i - f*g);
    float C =  (d*h - e*g);
    float det = a*A + b*B + c*C;
    float id = 1.0f/det;
    o[0]=A*id;            o[1]=-(b*i-c*h)*id;  o[2]= (b*f-c*e)*id;
    o[3]=B*id;            o[4]= (a*i-c*g)*id;  o[5]=-(a*f-c*d)*id;
    o[6]=C*id;            o[7]=-(a*h-b*g)*id;  o[8]= (a*e-b*d)*id;
}

__global__ void k_setup(const float* __restrict__ rots, const float* __restrict__ trans,
                        const float* __restrict__ intr, const float* __restrict__ prots,
                        const float* __restrict__ ptrans,
                        const float* __restrict__ c1b, const float* __restrict__ g1,
                        const float* __restrict__ b1,  const float* __restrict__ m1,
                        const float* __restrict__ v1,
                        const float* __restrict__ c2b, const float* __restrict__ g2,
                        const float* __restrict__ b2,  const float* __restrict__ m2,
                        const float* __restrict__ v2) {
    int t = threadIdx.x;
    if (t < NCAM) {
        float iK[9], iPR[9], comb[9];
        inv3(intr + t*9, iK);
        inv3(prots + t*9, iPR);
        const float* R = rots + t*9;
        #pragma unroll
        for (int r = 0; r < 3; r++)
            #pragma unroll
            for (int c = 0; c < 3; c++)
                comb[r*3+c] = R[r*3+0]*iK[0*3+c] + R[r*3+1]*iK[1*3+c] + R[r*3+2]*iK[2*3+c];
        float* o = g_cam + t*24;
        #pragma unroll
        for (int j = 0; j < 9; j++) o[j]   = comb[j];
        #pragma unroll
        for (int j = 0; j < 9; j++) o[9+j] = iPR[j];
        o[18]=trans[t*3+0]; o[19]=trans[t*3+1]; o[20]=trans[t*3+2];
        o[21]=ptrans[t*3+0]; o[22]=ptrans[t*3+1]; o[23]=ptrans[t*3+2];
    }
    if (t < FC) {
        float s1 = g1[t]*rsqrtf(v1[t] + 1e-3f);
        g_sc1[t] = s1;
        g_sh1[t] = (c1b[t] - m1[t])*s1 + b1[t];
        float s2 = g2[t]*rsqrtf(v2[t] + 1e-3f);
        g_sc2[t] = s2;
        g_sh2[t] = (c2b[t] - m2[t])*s2 + b2[t];
    }
    if (t == 0) g_cnt = 0;
}

// ---------------- weight transpose: [oc][ic][3][3] -> [s*128+ic][oc] ------------
__global__ void k_wtrans(const float* __restrict__ w1, const float* __restrict__ w2) {
    int i = blockIdx.x * 256 + threadIdx.x;
    int k  = i >> 7, oc = i & 127;
    int s  = k >> 7, ic = k & 127;
    int src = oc*KTOT + ic*9 + s;
    g_wt1[i] = w1[src];
    g_wt2[i] = w2[src];
}

// ---------------- conv3x3 implicit GEMM (round-9 measured-best shape) ----------
// grid (44 px-tiles, 6 images), block 256 = 16x16, micro-tile 8 oc x 4 px.
__global__ void k_conv3g(const float* __restrict__ feats, int layer) {
    __shared__ float sW[16][128];
    __shared__ float sX[16][64];
    const float* in_ = layer ? g_x1 : feats;
    const float* wt  = layer ? g_wt2 : g_wt1;
    float*       out = layer ? g_x2  : g_x1;
    const float* sc  = layer ? g_sc2 : g_sc1;
    const float* sh  = layer ? g_sh2 : g_sh1;

    int p0 = blockIdx.x * 64;
    int n  = blockIdx.y;
    int tid = threadIdx.x;
    int tx = tid & 15;
    int ty = tid >> 4;

    float acc[8][4];
    #pragma unroll
    for (int i = 0; i < 8; i++)
        #pragma unroll
        for (int j = 0; j < 4; j++) acc[i][j] = 0.0f;

    const float* inBase = in_ + n*FC*NPIX;

    int kkU[4], ppU[4], hU[4], wU[4];
    #pragma unroll
    for (int u = 0; u < 4; u++) {
        int e  = tid + u*256;
        kkU[u] = e >> 6; ppU[u] = e & 63;
        int p = p0 + ppU[u];
        hU[u] = p / FW; wU[u] = p - hU[u]*FW;
    }

    for (int s = 0; s < 9; s++) {
        int dh = s/3 - 1, dw = s%3 - 1;
        int doff = dh*FW + dw;
        bool valU[4];
        #pragma unroll
        for (int u = 0; u < 4; u++) {
            int hh = hU[u] + dh, ww = wU[u] + dw;
            valU[u] = ((unsigned)hh < FH) && ((unsigned)ww < FW);
        }
        for (int ic0 = 0; ic0 < FC; ic0 += 16) {
            __syncthreads();
            {
                int k0 = s*FC + ic0;
                #pragma unroll
                for (int u = 0; u < 2; u++) {
                    int e  = tid + u*256;
                    int kk = e >> 5, cv = e & 31;
                    ((float4*)&sW[kk][0])[cv] = ((const float4*)&wt[(k0+kk)*FC])[cv];
                }
            }
            #pragma unroll
            for (int u = 0; u < 4; u++) {
                float v = valU[u] ? inBase[(ic0+kkU[u])*NPIX + p0 + ppU[u] + doff] : 0.0f;
                sX[kkU[u]][ppU[u]] = v;
            }
            __syncthreads();
            #pragma unroll
            for (int kk = 0; kk < 16; kk++) {
                float4 xv = *(const float4*)&sX[kk][tx*4];
                float4 w0 = *(const float4*)&sW[kk][ty*8];
                float4 w1 = *(const float4*)&sW[kk][ty*8+4];
                float wv[8] = {w0.x,w0.y,w0.z,w0.w,w1.x,w1.y,w1.z,w1.w};
                float xr[4] = {xv.x,xv.y,xv.z,xv.w};
                #pragma unroll
                for (int i = 0; i < 8; i++)
                    #pragma unroll
                    for (int j = 0; j < 4; j++)
                        acc[i][j] = fmaf(wv[i], xr[j], acc[i][j]);
            }
        }
    }

    #pragma unroll
    for (int i = 0; i < 8; i++) {
        int oc = ty*8 + i;
        float scv = sc[oc], shv = sh[oc];
        float* op_ = out + (n*FC + oc)*NPIX + p0 + tx*4;
        #pragma unroll
        for (int j = 0; j < 4; j++)
            op_[j] = fmaxf(fmaf(acc[i][j], scv, shv), 0.0f);
    }
}

// ---------------- conv1x1 tiled GEMM ----------------
__global__ void k_conv1x1(const float* __restrict__ w3, const float* __restrict__ b3) {
    __shared__ float sW[16][64];
    __shared__ float sX[16][64];
    int p0  = blockIdx.x * 64;
    int oc0 = blockIdx.y * 64;
    int n   = blockIdx.z;
    int tid = threadIdx.x;
    int tx  = tid & 15;
    int ty  = tid >> 4;

    float acc[4][4];
    #pragma unroll
    for (int i = 0; i < 4; i++)
        #pragma unroll
        for (int j = 0; j < 4; j++) acc[i][j] = 0.0f;

    for (int k0 = 0; k0 < FC; k0 += 16) {
        #pragma unroll
        for (int i = tid; i < 16*64; i += 256) {
            int kk = i >> 6, oc = i & 63;
            int ocg = oc0 + oc;
            sW[kk][oc] = (ocg < OC3) ? w3[ocg*FC + k0 + kk] : 0.0f;
        }
        #pragma unroll
        for (int i = tid; i < 16*64; i += 256) {
            int kk = i >> 6, pp = i & 63;
            sX[kk][pp] = g_x2[(n*FC + k0 + kk)*NPIX + p0 + pp];
        }
        __syncthreads();
        #pragma unroll
        for (int kk = 0; kk < 16; kk++) {
            float xv[4], wv[4];
            #pragma unroll
            for (int j = 0; j < 4; j++) xv[j] = sX[kk][tx*4 + j];
            #pragma unroll
            for (int i = 0; i < 4; i++) wv[i] = sW[kk][ty*4 + i];
            #pragma unroll
            for (int i = 0; i < 4; i++)
                #pragma unroll
                for (int j = 0; j < 4; j++)
                    acc[i][j] = fmaf(wv[i], xv[j], acc[i][j]);
        }
        __syncthreads();
    }
    #pragma unroll
    for (int i = 0; i < 4; i++) {
        int oc = oc0 + ty*4 + i;
        if (oc < OC3) {
            float bb = __ldg(&b3[oc]);
            #pragma unroll
            for (int j = 0; j < 4; j++)
                g_logits[(n*OC3 + oc)*NPIX + p0 + tx*4 + j] = acc[i][j] + bb;
        }
    }
}

// ---------------- gaussian prep ----------------
__global__ void k_gauss() {
    int g = blockIdx.x * 128 + threadIdx.x;
    int n = g / NPIX;
    int p = g - n*NPIX;
    int h = p / FW;
    int w = p - h*FW;
    const float* L = g_logits + n*OC3*NPIX + p;

    float lg[DLEV];
    float mval = -1e30f;
    #pragma unroll
    for (int d = 0; d < DLEV; d++) { lg[d] = L[d*NPIX]; mval = fmaxf(mval, lg[d]); }
    float sum = 0.0f;
    #pragma unroll
    for (int d = 0; d < DLEV; d++) { lg[d] = __expf(lg[d] - mval); sum += lg[d]; }
    float inv = 1.0f / sum;

    const float* cm = g_cam + n*24;
    float c00=cm[0], c01=cm[1], c02=cm[2], c10=cm[3], c11=cm[4], c12=cm[5];
    float i00=cm[9], i01=cm[10], i02=cm[11], i10=cm[12], i11=cm[13], i12=cm[14];
    float i20=cm[15], i21=cm[16], i22=cm[17];
    float tx=cm[18], ty=cm[19];
    float ptx=cm[21], pty=cm[22], ptz=cm[23];
    float xs = (float)w * (703.0f/87.0f);
    float ys = (float)h * (255.0f/31.0f);
    float b0 = xs - ptx, b1 = ys - pty, b2 = -ptz;
    float bx = i00*b0 + i01*b1 + i02*b2;
    float by = i10*b0 + i11*b1 + i12*b2;
    float bz = i20*b0 + i21*b1 + i22*b2;
    float dx = i02, dy = i12, dz = i22;

    float mex = 0.0f, mey = 0.0f;
    #pragma unroll
    for (int d = 0; d < DLEV; d++) {
        float dep = 4.0f + (float)d;
        float p1x = bx + dep*dx, p1y = by + dep*dy, p1z = bz + dep*dz;
        float p2x = p1x*p1z, p2y = p1y*p1z;
        float gx = c00*p2x + c01*p2y + c02*p1z + tx;
        float gy = c10*p2x + c11*p2y + c12*p1z + ty;
        float pr = lg[d]*inv;
        mex += pr*gx; mey += pr*gy;
    }
    float cxx = 0.0f, cxy = 0.0f, cyy = 0.0f;
    #pragma unroll
    for (int d = 0; d < DLEV; d++) {
        float dep = 4.0f + (float)d;
        float p1x = bx + dep*dx, p1y = by + dep*dy, p1z = bz + dep*dz;
        float p2x = p1x*p1z, p2y = p1y*p1z;
        float gx = c00*p2x + c01*p2y + c02*p1z + tx;
        float gy = c10*p2x + c11*p2y + c12*p1z + ty;
        float ddx = mex - gx, ddy = mey - gy;
        float pr = lg[d]*inv;
        cxx += pr*ddx*ddx; cxy += pr*ddx*ddy; cyy += pr*ddy*ddy;
    }
    float a_ = cyy*(1.0f/9.0f) + 0.3f;
    float c_ = cxx*(1.0f/9.0f) + 0.3f;
    float b_ = cxy*(1.0f/9.0f);
    float det = a_*c_ - b_*b_;

    float opl = L[DLEV*NPIX];
    float op = 1.0f / (1.0f + __expf(-opl));
    bool msk = (op > 0.05f);
    if (msk) atomicAdd(&g_cnt, 1);
    bool valid = msk && (det > 0.0f);
    float idet = valid ? (1.0f/det) : 0.0f;

    float my = 50.0f - mey;
    float mx = 50.0f - mex;
    float qm = valid ? 2.0f*logf(255.0f*op) : -1e30f;

    g_pk0[g] = make_float4(my, mx, c_*idet, -b_*idet);
    g_pk1[g] = make_float4(a_*idet, op, qm, 0.0f);

    int r0 = 1, r1 = 0;
    if (valid) {
        float ext = sqrtf(fmaxf(qm, 0.0f)*a_) + 0.6f;
        r0 = max(0,  (int)ceilf(my - ext));
        r1 = min(99, (int)floorf(my + ext));
    }
    g_rmin[g] = r0;
    g_rmax[g] = r1;

    float4* cp4 = (float4*)(g_colors + g*OUTC);
    const float* fp_ = L + (DLEV+1)*NPIX;
    #pragma unroll
    for (int c = 0; c < OUTC; c += 4) {
        float4 v;
        v.x = fp_[(c+0)*NPIX];
        v.y = fp_[(c+1)*NPIX];
        v.z = fp_[(c+2)*NPIX];
        v.w = fp_[(c+3)*NPIX];
        cp4[c >> 2] = v;
    }
}

// ---------------- per-row ordered list build ----------------
__global__ void k_rows() {
    int r = blockIdx.x;
    int tid = threadIdx.x, lane = tid & 31, wid = tid >> 5;
    __shared__ int sCnt[8];
    __shared__ int sOff, sTot;
    if (tid == 0) sOff = 0;
    __syncthreads();
    for (int base = 0; base < G_TOT; base += 256) {
        int g = base + tid;
        bool f = (g_rmin[g] <= r) && (r <= g_rmax[g]);
        unsigned b = __ballot_sync(0xffffffffu, f);
        if (lane == 0) sCnt[wid] = __popc(b);
        __syncthreads();
        if (tid == 0) {
            int t = 0;
            #pragma unroll
            for (int i = 0; i < 8; i++) { int c = sCnt[i]; sCnt[i] = t; t += c; }
            sTot = t;
        }
        __syncthreads();
        if (f) {
            int pos = sOff + sCnt[wid] + __popc(b & ((1u << lane) - 1u));
            g_list[r*G_TOT + pos] = g;
        }
        __syncthreads();
        if (tid == 0) sOff += sTot;
        __syncthreads();
    }
    if (tid == 0) g_len[r] = sOff;
}

// ---------------- splat: phase-A hit masks drive sparse phase-B ----------------
// grid (100 rows, NSEG), block 416 = 13 warps.
// Phase A: warp w, lane = gaussian, covers px 8w..8w+7.
// Phase B: SAME warp covers SAME px (px = tid>>2, tq = tid&3); iterates only
//          the gaussians whose phase-A ballot hit this warp's 8 columns.
__global__ void k_splat6() {
    int r   = blockIdx.x;
    int seg = blockIdx.y;
    int tid  = threadIdx.x;
    int warp = tid >> 5;
    int lane = tid & 31;
    int col0 = warp * 8;
    float fi = (float)r;

    int px = tid >> 2;           // 0..103 (warp w -> px 8w..8w+7)
    int tq = tid & 3;            // channel quad group

    float pj[8], T[8];
    #pragma unroll
    for (int k = 0; k < 8; k++) {
        int c = col0 + k;
        pj[k] = (c < BEV_W) ? (float)c : 1e15f;
        T[k]  = 1.0f;
    }
    float acc[8][4];
    #pragma unroll
    for (int j = 0; j < 8; j++)
        #pragma unroll
        for (int jj = 0; jj < 4; jj++) acc[j][jj] = 0.0f;

    __shared__ int   sGid[32];
    __shared__ float sP[32][8];
    __shared__ float wBuf[32][105];
    __shared__ float cBuf[32][128];

    int len = g_len[r];
    int s0 = (len * seg) / NSEG;
    int s1 = (len * (seg+1)) / NSEG;
    const int* lst = g_list + r*G_TOT;

    for (int c0 = s0; c0 < s1; c0 += 32) {
        __syncthreads();
        if (tid < 32) {
            int idx = c0 + tid;
            if (idx < s1) {
                int gid = lst[idx];
                sGid[tid] = gid;
                float4 a = g_pk0[gid];
                float4 b = g_pk1[gid];
                sP[tid][0] = a.x; sP[tid][1] = a.y;
                sP[tid][2] = a.z; sP[tid][3] = a.w;
                sP[tid][4] = b.x; sP[tid][5] = b.y;
                sP[tid][6] = b.z;
            } else {
                sGid[tid] = 0;
                sP[tid][0] = 0.0f; sP[tid][1] = 0.0f;
                sP[tid][2] = 0.0f; sP[tid][3] = 0.0f;
                sP[tid][4] = 0.0f; sP[tid][5] = 0.0f;
                sP[tid][6] = -1e30f;
            }
        }
        __syncthreads();
        // stage colors: 32 gaussians x 128 ch = 1024 float4
        for (int i = tid; i < 1024; i += 416) {
            int g = i >> 5, cv = i & 31;
            *(float4*)&cBuf[g][cv*4] = *(const float4*)(g_colors + sGid[g]*OUTC + cv*4);
        }

        // ---- phase A: ordered weights via multiplicative scan ----
        float my = sP[lane][0], mxx = sP[lane][1];
        float A  = sP[lane][2], Bc  = sP[lane][3], Cc = sP[lane][4];
        float op = sP[lane][5], qm  = sP[lane][6];
        float dI = fi - my;
        float c1 = A*dI*dI;
        float c2 = 2.0f*Bc*dI;

        float al[8]; unsigned msk[8];
        #pragma unroll
        for (int k = 0; k < 8; k++) {
            float dJ = pj[k] - mxx;
            float q = c1 + c2*dJ + Cc*dJ*dJ;
            float a_v = 0.0f;
            if (q >= 0.0f && q <= qm + 1e-3f) {
                a_v = fminf(0.99f, op*__expf(-0.5f*q));
                if (a_v < (1.0f/255.0f)) a_v = 0.0f;
            }
            al[k] = a_v;
            msk[k] = __ballot_sync(0xffffffffu, a_v > 0.0f);
        }
        #pragma unroll
        for (int k = 0; k < 8; k++) {
            float wv = 0.0f;
            if (msk[k]) {                        // warp-uniform
                float incl = 1.0f - al[k];
                #pragma unroll
                for (int off = 1; off < 32; off <<= 1) {
                    float u = __shfl_up_sync(0xffffffffu, incl, off);
                    if (lane >= off) incl *= u;
                }
                float excl = __shfl_up_sync(0xffffffffu, incl, 1);
                if (lane == 0) excl = 1.0f;
                wv = al[k] * T[k] * excl;
                T[k] *= __shfl_sync(0xffffffffu, incl, 31);
            }
            wBuf[lane][col0 + k] = wv;
        }
        unsigned un = msk[0] | msk[1] | msk[2] | msk[3]
                    | msk[4] | msk[5] | msk[6] | msk[7];   // this warp's hit set
        __syncthreads();

        // ---- phase B: iterate only hit gaussians for this warp's 8 px ----
        while (un) {
            int g = __ffs(un) - 1;
            un &= un - 1;
            float w = wBuf[g][px];               // broadcast x4, conflict-free
            #pragma unroll
            for (int j = 0; j < 8; j++) {
                float4 col = *(const float4*)&cBuf[g][tq*4 + j*16];
                acc[j][0] = fmaf(w, col.x, acc[j][0]);
                acc[j][1] = fmaf(w, col.y, acc[j][1]);
                acc[j][2] = fmaf(w, col.z, acc[j][2]);
                acc[j][3] = fmaf(w, col.w, acc[j][3]);
            }
        }
    }

    if (px < BEV_W) {
        int p = r*BEV_W + px;
        #pragma unroll
        for (int j = 0; j < 8; j++) {
            int chb = tq*4 + j*16;
            #pragma unroll
            for (int jj = 0; jj < 4; jj++)
                g_sacc[seg][(chb + jj)*P_TOT + p] = acc[j][jj];
        }
    }
    if (lane == 0) {
        #pragma unroll
        for (int k = 0; k < 8; k++) {
            int c = col0 + k;
            if (c < BEV_W) g_sT[seg][r*BEV_W + c] = T[k];
        }
    }
}

// ---------------- combine segments ----------------
__global__ void k_combine(float* __restrict__ out) {
    int i = blockIdx.x * 256 + threadIdx.x;
    int p = i % P_TOT;
    float v = g_sacc[NSEG-1][i];
    #pragma unroll
    for (int s = NSEG-2; s >= 0; s--)
        v = g_sacc[s][i] + g_sT[s][p] * v;
    out[i] = v;
}

__global__ void k_count(float* __restrict__ dst) {
    dst[0] = (float)g_cnt;
}

// ---------------- launch ----------------
extern "C" void kernel_launch(void* const* d_in, const int* in_sizes, int n_in,
                              void* d_out, int out_size) {
    const float* rots   = (const float*)d_in[0];
    const float* trans  = (const float*)d_in[1];
    const float* intr   = (const float*)d_in[2];
    const float* prots  = (const float*)d_in[3];
    const float* ptrans = (const float*)d_in[4];
    const float* feats  = (const float*)d_in[5];
    const float* c1w = (const float*)d_in[6];
    const float* c1b = (const float*)d_in[7];
    const float* g1  = (const float*)d_in[8];
    const float* b1  = (const float*)d_in[9];
    const float* m1  = (const float*)d_in[10];
    const float* v1  = (const float*)d_in[11];
    const float* c2w = (const float*)d_in[12];
    const float* c2b = (const float*)d_in[13];
    const float* g2  = (const float*)d_in[14];
    const float* b2  = (const float*)d_in[15];
    const float* m2  = (const float*)d_in[16];
    const float* v2  = (const float*)d_in[17];
    const float* c3w = (const float*)d_in[18];
    const float* c3b = (const float*)d_in[19];
    float* out = (float*)d_out;

    k_setup<<<1, 256>>>(rots, trans, intr, prots, ptrans,
                        c1b, g1, b1, m1, v1, c2b, g2, b2, m2, v2);
    k_wtrans<<<576, 256>>>(c1w, c2w);
    k_conv3g<<<dim3(44, 6), 256>>>(feats, 0);
    k_conv3g<<<dim3(44, 6), 256>>>(feats, 1);
    k_conv1x1<<<dim3(44, 3, 6), 256>>>(c3w, c3b);
    k_gauss<<<132, 128>>>();
    k_rows<<<BEV_H, 256>>>();
    k_splat6<<<dim3(BEV_H, NSEG), 416>>>();
    k_combine<<<5000, 256>>>(out);
    if (out_size > P_TOT*OUTC)
        k_count<<<1, 1>>>(out + P_TOT*OUTC);
}